// round 4
// baseline (speedup 1.0000x reference)
#include <cuda_runtime.h>
#include <cstdint>

// Problem constants
#define N_PIX 4194304      // 4*4*512*512
#define NQ    1048576      // N_PIX / 4  (float4 groups)
#define NB    101          // bins / categories

// ---------------------------------------------------------------------------
// JAX *partitionable* threefry bits for 32-bit draws, key = jax.random.key(1):
//   (k1,k2) = (0,1);  ks0=0, ks1=1, ks2 = 0^1^0x1BD11BDA = 0x1BD11BDB
//   per element i (size < 2^32): counts_hi = 0, counts_lo = i
//   (y0,y1) = threefry2x32((0,1), (0,i));  bits = y0 ^ y1
// ---------------------------------------------------------------------------
__device__ __forceinline__ uint32_t threefry_bits(uint32_t i) {
    const uint32_t ks0 = 0u;
    const uint32_t ks1 = 1u;
    const uint32_t ks2 = 0x1BD11BDBu;

    uint32_t x0 = 0u + ks0;   // counts_hi + ks0
    uint32_t x1 = i  + ks1;   // counts_lo + ks1

#define TF_ROUND(r) do { x0 += x1; x1 = __funnelshift_l(x1, x1, (r)); x1 ^= x0; } while (0)

    // block 1: rotations 13,15,26,6 ; inject ks1, ks2+1
    TF_ROUND(13); TF_ROUND(15); TF_ROUND(26); TF_ROUND(6);
    x0 += ks1; x1 += ks2 + 1u;
    // block 2: rotations 17,29,16,24 ; inject ks2, ks0+2
    TF_ROUND(17); TF_ROUND(29); TF_ROUND(16); TF_ROUND(24);
    x0 += ks2; x1 += ks0 + 2u;
    // block 3: 13,15,26,6 ; inject ks0, ks1+3
    TF_ROUND(13); TF_ROUND(15); TF_ROUND(26); TF_ROUND(6);
    x0 += ks0; x1 += ks1 + 3u;
    // block 4: 17,29,16,24 ; inject ks1, ks2+4
    TF_ROUND(17); TF_ROUND(29); TF_ROUND(16); TF_ROUND(24);
    x0 += ks1; x1 += ks2 + 4u;
    // block 5: 13,15,26,6 ; inject ks2, ks0+5
    TF_ROUND(13); TF_ROUND(15); TF_ROUND(26); TF_ROUND(6);
    x0 += ks2; x1 += ks0 + 5u;

#undef TF_ROUND
    return x0 ^ x1;           // partitionable 32-bit combine
}

// digitize(x, arange(0,0.5,0.005)) = # of float32 edges e(j)=j*0.005f with e<=x
__device__ __forceinline__ int refl_bin(float xv) {
    int r = (int)(xv * 200.0f) + 1;
    r = min(r, 100);
    if (r < 100 && (float)r * 0.005f <= xv) ++r;
    if ((float)(r - 1) * 0.005f > xv) --r;
    return r;   // in [0, 100]
}

// lower_bound over a 101-element shared row: first j with row[j] >= u (may be 101)
__device__ __forceinline__ int lb101(const float* __restrict__ row, float u) {
    int lo = 0, len = NB;          // 101 -> 50 -> 25 -> 12 -> 6 -> 3 -> 1 -> 0
#pragma unroll
    for (int it = 0; it < 7; ++it) {
        int half = len >> 1;
        int mid  = lo + half;
        bool go  = row[mid] < u;
        lo  = go ? (mid + 1)        : lo;
        len = go ? (len - half - 1) : half;
    }
    return lo;
}

__global__ __launch_bounds__(1024, 2)
void noise_model_kernel(const float4* __restrict__ x4,
                        const float*  __restrict__ nm,
                        float4* __restrict__ out4) {
    __shared__ float cdf[NB * NB];   // 40,804 bytes

    const int tid = threadIdx.x;

    // Per-block CDF build: thread t does sequential (left-to-right) cumsum of
    // row t. Unroll shrinks loop overhead; FADD order is unchanged.
    if (tid < NB) {
        const float* rowp = nm  + tid * NB;
        float*       crow = cdf + tid * NB;
        float s = 0.0f;
#pragma unroll 4
        for (int j = 0; j < NB; ++j) {
            s += rowp[j];
            crow[j] = s;
        }
    }
    __syncthreads();

    const int stride = blockDim.x * gridDim.x;
    for (int g = blockIdx.x * blockDim.x + tid; g < NQ; g += stride) {
        const uint32_t base = (uint32_t)g * 4u;

        // 4 independent threefry evaluations (ILP)
        uint32_t b0 = threefry_bits(base + 0u);
        uint32_t b1 = threefry_bits(base + 1u);
        uint32_t b2 = threefry_bits(base + 2u);
        uint32_t b3 = threefry_bits(base + 3u);

        float u0 = __uint_as_float((b0 >> 9) | 0x3f800000u) - 1.0f;
        float u1 = __uint_as_float((b1 >> 9) | 0x3f800000u) - 1.0f;
        float u2 = __uint_as_float((b2 >> 9) | 0x3f800000u) - 1.0f;
        float u3 = __uint_as_float((b3 >> 9) | 0x3f800000u) - 1.0f;

        float4 xv = x4[g];

        int i0 = min(lb101(&cdf[refl_bin(xv.x) * NB], u0), NB - 1);
        int i1 = min(lb101(&cdf[refl_bin(xv.y) * NB], u1), NB - 1);
        int i2 = min(lb101(&cdf[refl_bin(xv.z) * NB], u2), NB - 1);
        int i3 = min(lb101(&cdf[refl_bin(xv.w) * NB], u3), NB - 1);

        float4 o;
        o.x = -0.0101f + 0.0002f * (float)i0;
        o.y = -0.0101f + 0.0002f * (float)i1;
        o.z = -0.0101f + 0.0002f * (float)i2;
        o.w = -0.0101f + 0.0002f * (float)i3;
        out4[g] = o;
    }
}

extern "C" void kernel_launch(void* const* d_in, const int* in_sizes, int n_in,
                              void* d_out, int out_size) {
    // Disambiguate inputs by size: x has 4194304 elems, noise_matrix has 10201.
    const float* a = (const float*)d_in[0];
    const float* b = (const float*)d_in[1];
    const float* x  = a;
    const float* nm = b;
    if (n_in >= 2 && in_sizes[0] < in_sizes[1]) { x = b; nm = a; }
    float* out = (float*)d_out;
    (void)out_size;

    noise_model_kernel<<<296, 1024>>>((const float4*)x, nm, (float4*)out);
}